// round 13
// baseline (speedup 1.0000x reference)
#include <cuda_runtime.h>
#include <cuda_fp16.h>
#include <cstdint>
#include <cstddef>

// ---------------------------------------------------------------------------
// TargetCentricAttention: B=4, S=2048, D=1024, fp32 in/out.
// Round-13: 128x256 CTA tiles (512 threads, 16 warps) to cut L2 operand
// traffic per MAC by 25% (GEMMs measured L2-bandwidth-bound at 128x128).
// compute_chunk reverted to R9 form (R12 intra-warp pipelining was neutral).
// Base: fp16 m16n8k16, K-chunk 64, 3-stage cp.async pipeline, fused
// exp+colsum epilogue in scoresT, 1/S folded into vT.
// ---------------------------------------------------------------------------

namespace {
constexpr int BATCH = 4;
constexpr int SEQ   = 2048;
constexpr int DIM   = 1024;
constexpr int MTOK  = BATCH * SEQ;   // 8192

constexpr int BM = 128, BN = 256;
constexpr int NTHREADS = 512;        // 16 warps: 4(M) x 4(N); warp tile 32x64
constexpr int BKH = 64;              // K halves per chunk

constexpr int ROW_B   = 144;         // 128 B payload + 16 pad (9*16)
constexpr int TILE_A  = BM * ROW_B;  // 18432
constexpr int TILE_BB = BN * ROW_B;  // 36864
constexpr int BUF_B   = TILE_A + TILE_BB;       // 55296 per stage
constexpr int NSTAGE  = 3;
constexpr unsigned SMEM_DYN = NSTAGE * BUF_B;   // 165888 -> 1 CTA/SM, 16 warps
}

// Scratch (allocation-free rule: __device__ globals)
__device__ __half g_x [(size_t)MTOK * DIM];
__device__ __half g_wt[(size_t)3 * DIM * DIM];     // Wq|Wk|Wv
__device__ __half g_q [(size_t)MTOK * DIM];
__device__ __half g_k [(size_t)MTOK * DIM];
__device__ __half g_vt[(size_t)DIM * MTOK];        // [d][tok], scaled by 1/S later
__device__ __half g_wh[(size_t)BATCH * SEQ * SEQ]; // e = exp(scores^T)
__device__ float  g_S [(size_t)MTOK];              // column sums (atomic)

__device__ __forceinline__ uint32_t smem_u32(const void* p) {
    uint32_t a;
    asm("{ .reg .u64 t; cvta.to.shared.u64 t, %1; cvt.u32.u64 %0, t; }" : "=r"(a) : "l"(p));
    return a;
}
__device__ __forceinline__ void cpasync16(uint32_t dst, const void* src) {
    asm volatile("cp.async.cg.shared.global [%0], [%1], 16;" :: "r"(dst), "l"(src));
}
__device__ __forceinline__ void cpcommit() {
    asm volatile("cp.async.commit_group;" ::: "memory");
}
template <int N>
__device__ __forceinline__ void cpwait() {
    asm volatile("cp.async.wait_group %0;" :: "n"(N) : "memory");
}
__device__ __forceinline__ void ldsm4(uint32_t r[4], uint32_t addr) {
    asm volatile("ldmatrix.sync.aligned.m8n8.x4.shared.b16 {%0,%1,%2,%3}, [%4];"
                 : "=r"(r[0]), "=r"(r[1]), "=r"(r[2]), "=r"(r[3]) : "r"(addr));
}
__device__ __forceinline__ void mma_f16(float c[4],
                                        uint32_t a0, uint32_t a1, uint32_t a2, uint32_t a3,
                                        uint32_t b0, uint32_t b1) {
    asm volatile(
        "mma.sync.aligned.m16n8k16.row.col.f32.f16.f16.f32 "
        "{%0,%1,%2,%3}, {%4,%5,%6,%7}, {%8,%9}, {%0,%1,%2,%3};"
        : "+f"(c[0]), "+f"(c[1]), "+f"(c[2]), "+f"(c[3])
        : "r"(a0), "r"(a1), "r"(a2), "r"(a3), "r"(b0), "r"(b1));
}

// ---------------------------------------------------------------------------
// Staging: NROWS(row) x 64(k-halves) tile, 128 B payload / 144 B stride.
// NROWS*8 16-byte tasks over 512 threads.
// ---------------------------------------------------------------------------
template <int NROWS>
__device__ __forceinline__ void stage_op(uint32_t dstb, const __half* __restrict__ S,
                                         int rowBase, int ld, int kt, int t) {
#pragma unroll
    for (int i = 0; i < NROWS * 8 / NTHREADS; i++) {
        int task = t + i * NTHREADS;
        int row = task >> 3, k8 = task & 7;
        cpasync16(dstb + row * ROW_B + k8 * 16,
                  S + (size_t)(rowBase + row) * ld + kt + k8 * 8);
    }
}

// ---------------------------------------------------------------------------
// One 128x256x64 chunk per CTA; per-warp 32x64 (identical to R9).
// ---------------------------------------------------------------------------
__device__ __forceinline__ void compute_chunk(uint32_t As, uint32_t Bs,
                                              float acc[2][8][4], int warp, int lane) {
    const int wm = (warp & 3) * 32, wn = (warp >> 2) * 64;
    const uint32_t aBase = As + (uint32_t)(wm + (lane & 15)) * ROW_B
                              + (uint32_t)(lane >> 4) * 16;
    const uint32_t bBase = Bs + (uint32_t)(wn + (lane >> 4) * 8 + (lane & 7)) * ROW_B
                              + (uint32_t)((lane >> 3) & 1) * 16;
#pragma unroll
    for (int ks = 0; ks < 4; ks++) {
        const uint32_t ko = (uint32_t)ks * 32;
        uint32_t a0[4], a1[4], b[2][4];
        ldsm4(a0, aBase + ko);
        ldsm4(a1, aBase + 16 * ROW_B + ko);
        ldsm4(b[0], bBase + ko);
#pragma unroll
        for (int p = 0; p < 4; p++) {
            if (p < 3) ldsm4(b[(p + 1) & 1], bBase + (uint32_t)(p + 1) * (16 * ROW_B) + ko);
            const uint32_t* bp = b[p & 1];
            mma_f16(acc[0][2 * p],     a0[0], a0[1], a0[2], a0[3], bp[0], bp[1]);
            mma_f16(acc[0][2 * p + 1], a0[0], a0[1], a0[2], a0[3], bp[2], bp[3]);
            mma_f16(acc[1][2 * p],     a1[0], a1[1], a1[2], a1[3], bp[0], bp[1]);
            mma_f16(acc[1][2 * p + 1], a1[0], a1[1], a1[2], a1[3], bp[2], bp[3]);
        }
    }
}

// ---------------------------------------------------------------------------
// GEMM core (128x256 CTA tile). EPI: 0 fp32+colbias | 1 fp16+colbias |
//   2 fp16+rowbias | 3 fp16=exp(alpha*acc) + fused column sums -> gS | 4 fp32.
// ---------------------------------------------------------------------------
template <int EPI>
__device__ __forceinline__ void tc_gemm(const __half* __restrict__ A,
                                        const __half* __restrict__ B,
                                        void* __restrict__ Cv,
                                        int Kdim, int lda, int ldb, int ldc,
                                        float alpha, const float* __restrict__ bias,
                                        int mBase, int nBase,
                                        float* __restrict__ gS = nullptr) {
    extern __shared__ char dsm[];
    const uint32_t sb = smem_u32(dsm);
    const int t = threadIdx.x, warp = t >> 5, lane = t & 31;

    float acc[2][8][4];
#pragma unroll
    for (int i = 0; i < 2; i++)
#pragma unroll
        for (int j = 0; j < 8; j++)
#pragma unroll
            for (int q = 0; q < 4; q++) acc[i][j][q] = 0.0f;

    const int NC = Kdim / BKH;

    stage_op<BM>(sb, A, mBase, lda, 0, t);
    stage_op<BN>(sb + TILE_A, B, nBase, ldb, 0, t);
    cpcommit();
    stage_op<BM>(sb + BUF_B, A, mBase, lda, BKH, t);
    stage_op<BN>(sb + BUF_B + TILE_A, B, nBase, ldb, BKH, t);
    cpcommit();

    uint32_t oCur = 0, oNext = BUF_B, oFree = 2u * BUF_B;

    for (int c = 0; c < NC; c++) {
        if (c + 1 < NC) cpwait<1>(); else cpwait<0>();
        __syncthreads();
        if (c + 2 < NC) {
            stage_op<BM>(sb + oFree, A, mBase, lda, (c + 2) * BKH, t);
            stage_op<BN>(sb + oFree + TILE_A, B, nBase, ldb, (c + 2) * BKH, t);
            cpcommit();
        }
        compute_chunk(sb + oCur, sb + oCur + TILE_A, acc, warp, lane);
        uint32_t tmp = oCur; oCur = oNext; oNext = oFree; oFree = tmp;
    }

    // epilogue
    const int g = lane >> 2, tg = lane & 3;
    const int wm = (warp & 3) * 32, wn = (warp >> 2) * 64;
    float cs[8][2];
    if (EPI == 3) {
#pragma unroll
        for (int j = 0; j < 8; j++) { cs[j][0] = 0.f; cs[j][1] = 0.f; }
    }
#pragma unroll
    for (int mi = 0; mi < 2; mi++) {
#pragma unroll
        for (int ni = 0; ni < 8; ni++) {
            const int row = mBase + wm + mi * 16 + g;
            const int col = nBase + wn + ni * 8 + tg * 2;
            float v0, v1, v2, v3;
            if (EPI == 0 || EPI == 1) {
                float2 bz = *(const float2*)(bias + col);
                v0 = fmaf(alpha, acc[mi][ni][0], bz.x);
                v1 = fmaf(alpha, acc[mi][ni][1], bz.y);
                v2 = fmaf(alpha, acc[mi][ni][2], bz.x);
                v3 = fmaf(alpha, acc[mi][ni][3], bz.y);
            } else if (EPI == 2) {
                float blo = bias[row], bhi = bias[row + 8];
                v0 = fmaf(alpha, acc[mi][ni][0], blo);
                v1 = fmaf(alpha, acc[mi][ni][1], blo);
                v2 = fmaf(alpha, acc[mi][ni][2], bhi);
                v3 = fmaf(alpha, acc[mi][ni][3], bhi);
            } else if (EPI == 3) {
                v0 = __expf(alpha * acc[mi][ni][0]);
                v1 = __expf(alpha * acc[mi][ni][1]);
                v2 = __expf(alpha * acc[mi][ni][2]);
                v3 = __expf(alpha * acc[mi][ni][3]);
                cs[ni][0] += v0 + v2;
                cs[ni][1] += v1 + v3;
            } else {
                v0 = alpha * acc[mi][ni][0];
                v1 = alpha * acc[mi][ni][1];
                v2 = alpha * acc[mi][ni][2];
                v3 = alpha * acc[mi][ni][3];
            }
            if (EPI == 0 || EPI == 4) {
                float* C = (float*)Cv;
                *(float2*)(C + (size_t)row * ldc + col)       = make_float2(v0, v1);
                *(float2*)(C + (size_t)(row + 8) * ldc + col) = make_float2(v2, v3);
            } else {
                __half* C = (__half*)Cv;
                *(__half2*)(C + (size_t)row * ldc + col)       = __floats2half2_rn(v0, v1);
                *(__half2*)(C + (size_t)(row + 8) * ldc + col) = __floats2half2_rn(v2, v3);
            }
        }
    }

    if (EPI == 3) {
        // reduce 8 g-lanes per column; 4 M-warps via smem [4][256]; atomics.
        float* partial = reinterpret_cast<float*>(dsm);
        __syncthreads();
#pragma unroll
        for (int ni = 0; ni < 8; ni++) {
#pragma unroll
            for (int j = 0; j < 2; j++) {
                float s = cs[ni][j];
                s += __shfl_down_sync(0xffffffffu, s, 16);
                s += __shfl_down_sync(0xffffffffu, s, 8);
                s += __shfl_down_sync(0xffffffffu, s, 4);
                if (lane < 4)
                    partial[(warp & 3) * BN + wn + ni * 8 + lane * 2 + j] = s;
            }
        }
        __syncthreads();
        if (t < BN) {
            float S = partial[t] + partial[BN + t] + partial[2 * BN + t] + partial[3 * BN + t];
            atomicAdd(gS + nBase + t, S);
        }
    }
}

// ---------------------------------------------------------------------------
// Kernels
// ---------------------------------------------------------------------------

// Fused fp32 -> fp16 conversion (x, Wq|Wk|Wv); also zeroes g_S.
__global__ void __launch_bounds__(256) cvt_all_kernel(
    const float* __restrict__ x, const float* __restrict__ Wq,
    const float* __restrict__ Wk, const float* __restrict__ Wv) {
    const int XN4 = MTOK * DIM / 4, WN4 = DIM * DIM / 4;
    int i = blockIdx.x * blockDim.x + threadIdx.x;
    if (i < MTOK / 4)
        reinterpret_cast<float4*>(g_S)[i] = make_float4(0.f, 0.f, 0.f, 0.f);
    const float* src;
    __half* dst;
    int j;
    if (i < XN4)                { src = x;  dst = g_x;  j = i; }
    else if (i < XN4 + WN4)     { src = Wq; dst = g_wt; j = i - XN4; }
    else if (i < XN4 + 2 * WN4) { src = Wk; dst = g_wt + (size_t)DIM * DIM;     j = i - XN4 - WN4; }
    else if (i < XN4 + 3 * WN4) { src = Wv; dst = g_wt + (size_t)2 * DIM * DIM; j = i - XN4 - 2 * WN4; }
    else return;
    float4 v = reinterpret_cast<const float4*>(src)[j];
    reinterpret_cast<__half2*>(dst)[j * 2]     = __floats2half2_rn(v.x, v.y);
    reinterpret_cast<__half2*>(dst)[j * 2 + 1] = __floats2half2_rn(v.z, v.w);
}

// Q/K projections: M=MTOK (tiles of 128), N=DIM (tiles of 256), fp16 out.
__global__ void __launch_bounds__(NTHREADS, 1) qk_kernel(
    const float* __restrict__ bq, const float* __restrict__ bk) {
    const float* bias = blockIdx.z == 0 ? bq : bk;
    __half* out       = blockIdx.z == 0 ? g_q : g_k;
    const __half* W   = g_wt + (size_t)blockIdx.z * DIM * DIM;
    tc_gemm<1>(g_x, W, out, DIM, DIM, DIM, DIM, 1.0f, bias,
               blockIdx.y * BM, blockIdx.x * BN);
}

// vT = Wv x^T + bv: M=DIM (tiles of 128), N=MTOK (tiles of 256), row bias.
__global__ void __launch_bounds__(NTHREADS, 1) vt_kernel(const float* __restrict__ bv) {
    tc_gemm<2>(g_wt + (size_t)2 * DIM * DIM, g_x, g_vt,
               DIM, DIM, DIM, MTOK, 1.0f, bv,
               blockIdx.y * BM, blockIdx.x * BN);
}

// e = exp(scores^T), fp16 out; fused column-sum atomics into g_S.
// M=kt (tiles of 128), N=q (tiles of 256).
__global__ void __launch_bounds__(NTHREADS, 1) scoresT_kernel() {
    int b = blockIdx.z;
    tc_gemm<3>(g_k + (size_t)b * SEQ * DIM,
               g_q + (size_t)b * SEQ * DIM,
               g_wh + (size_t)b * SEQ * SEQ,
               DIM, DIM, DIM, SEQ, 0.03125f, nullptr,
               blockIdx.y * BM, blockIdx.x * BN,
               g_S + (size_t)b * SEQ);
}

// Scale vT columns by 1/S (uint4 loads, float4 S reads).
__global__ void __launch_bounds__(256) vtscale_kernel() {
    size_t i = ((size_t)blockIdx.x * blockDim.x + threadIdx.x) * 8;
    int tok = (int)(i % MTOK);
    uint4* p = reinterpret_cast<uint4*>(g_vt + i);
    uint4 u = *p;
    float4 s0 = *reinterpret_cast<const float4*>(g_S + tok);
    float4 s1 = *reinterpret_cast<const float4*>(g_S + tok + 4);
    __half2* h = reinterpret_cast<__half2*>(&u);
    float2 v;
    v = __half22float2(h[0]); h[0] = __floats2half2_rn(v.x * __frcp_rn(s0.x), v.y * __frcp_rn(s0.y));
    v = __half22float2(h[1]); h[1] = __floats2half2_rn(v.x * __frcp_rn(s0.z), v.y * __frcp_rn(s0.w));
    v = __half22float2(h[2]); h[2] = __floats2half2_rn(v.x * __frcp_rn(s1.x), v.y * __frcp_rn(s1.y));
    v = __half22float2(h[3]); h[3] = __floats2half2_rn(v.x * __frcp_rn(s1.z), v.y * __frcp_rn(s1.w));
    *p = u;
}

// out = e . vT'^T: M=kt (tiles of 128), N=d (tiles of 256), fp32 out.
__global__ void __launch_bounds__(NTHREADS, 1) out_kernel(float* __restrict__ out) {
    int b = blockIdx.z;
    tc_gemm<4>(g_wh + (size_t)b * SEQ * SEQ,
               g_vt + (size_t)b * SEQ,
               out + (size_t)b * SEQ * DIM,
               SEQ, SEQ, MTOK, DIM, 1.0f, nullptr,
               blockIdx.y * BM, blockIdx.x * BN);
}

// ---------------------------------------------------------------------------

extern "C" void kernel_launch(void* const* d_in, const int* in_sizes, int n_in,
                              void* d_out, int out_size) {
    (void)in_sizes; (void)n_in; (void)out_size;
    const float* x  = (const float*)d_in[0];
    const float* Wq = (const float*)d_in[1];
    const float* bq = (const float*)d_in[2];
    const float* Wk = (const float*)d_in[3];
    const float* bk = (const float*)d_in[4];
    const float* Wv = (const float*)d_in[5];
    const float* bv = (const float*)d_in[6];
    float* out = (float*)d_out;

    cudaFuncSetAttribute(qk_kernel,      cudaFuncAttributeMaxDynamicSharedMemorySize, SMEM_DYN);
    cudaFuncSetAttribute(vt_kernel,      cudaFuncAttributeMaxDynamicSharedMemorySize, SMEM_DYN);
    cudaFuncSetAttribute(scoresT_kernel, cudaFuncAttributeMaxDynamicSharedMemorySize, SMEM_DYN);
    cudaFuncSetAttribute(out_kernel,     cudaFuncAttributeMaxDynamicSharedMemorySize, SMEM_DYN);

    {
        int total4 = (MTOK * DIM + 3 * DIM * DIM) / 4;
        cvt_all_kernel<<<(total4 + 255) / 256, 256>>>(x, Wq, Wk, Wv);
    }

    dim3 blk(NTHREADS);
    qk_kernel<<<dim3(DIM / BN, MTOK / BM, 2), blk, SMEM_DYN>>>(bq, bk);
    vt_kernel<<<dim3(MTOK / BN, DIM / BM, 1), blk, SMEM_DYN>>>(bv);
    scoresT_kernel<<<dim3(SEQ / BN, SEQ / BM, BATCH), blk, SMEM_DYN>>>();
    vtscale_kernel<<<dim3((int)((size_t)DIM * MTOK / 8 / 256)), dim3(256)>>>();
    out_kernel<<<dim3(DIM / BN, SEQ / BM, BATCH), blk, SMEM_DYN>>>(out);
}

// round 14
// speedup vs baseline: 1.1845x; 1.1845x over previous
#include <cuda_runtime.h>
#include <cuda_fp16.h>
#include <cstdint>
#include <cstddef>

// ---------------------------------------------------------------------------
// TargetCentricAttention: B=4, S=2048, D=1024, fp32 in/out.
// Round-14: revert GEMM core to R9 champion config (128x128 tiles, 256 thr,
// 2 CTAs/SM, 3-stage cp.async); keep inv-fold into vtscale (R12). NEW:
// vt_kernel forked onto a second stream (event fork/join, graph-capturable)
// to fill qk/scoresT wave tails with independent work.
// ---------------------------------------------------------------------------

namespace {
constexpr int BATCH = 4;
constexpr int SEQ   = 2048;
constexpr int DIM   = 1024;
constexpr int MTOK  = BATCH * SEQ;   // 8192

constexpr int NTHREADS = 256;        // 8 warps: 4(M) x 2(N), 128x128 CTA tile
constexpr int BKH     = 64;          // K halves per chunk

constexpr int ROW_B  = 144;          // 128 B payload + 16 pad (9*16)
constexpr int TILE_B = 128 * ROW_B;  // 18432
constexpr int BUF_B  = 2 * TILE_B;
constexpr int NSTAGE = 3;
constexpr unsigned SMEM_DYN = NSTAGE * BUF_B;  // 110592 -> 2 CTAs/SM
}

// Scratch (allocation-free rule: __device__ globals)
__device__ __half g_x [(size_t)MTOK * DIM];
__device__ __half g_wt[(size_t)3 * DIM * DIM];     // Wq|Wk|Wv
__device__ __half g_q [(size_t)MTOK * DIM];
__device__ __half g_k [(size_t)MTOK * DIM];
__device__ __half g_vt[(size_t)DIM * MTOK];        // [d][tok], scaled by 1/S later
__device__ __half g_wh[(size_t)BATCH * SEQ * SEQ]; // e = exp(scores^T)
__device__ float  g_S [(size_t)MTOK];              // column sums (atomic)

__device__ __forceinline__ uint32_t smem_u32(const void* p) {
    uint32_t a;
    asm("{ .reg .u64 t; cvta.to.shared.u64 t, %1; cvt.u32.u64 %0, t; }" : "=r"(a) : "l"(p));
    return a;
}
__device__ __forceinline__ void cpasync16(uint32_t dst, const void* src) {
    asm volatile("cp.async.cg.shared.global [%0], [%1], 16;" :: "r"(dst), "l"(src));
}
__device__ __forceinline__ void cpcommit() {
    asm volatile("cp.async.commit_group;" ::: "memory");
}
template <int N>
__device__ __forceinline__ void cpwait() {
    asm volatile("cp.async.wait_group %0;" :: "n"(N) : "memory");
}
__device__ __forceinline__ void ldsm4(uint32_t r[4], uint32_t addr) {
    asm volatile("ldmatrix.sync.aligned.m8n8.x4.shared.b16 {%0,%1,%2,%3}, [%4];"
                 : "=r"(r[0]), "=r"(r[1]), "=r"(r[2]), "=r"(r[3]) : "r"(addr));
}
__device__ __forceinline__ void mma_f16(float c[4],
                                        uint32_t a0, uint32_t a1, uint32_t a2, uint32_t a3,
                                        uint32_t b0, uint32_t b1) {
    asm volatile(
        "mma.sync.aligned.m16n8k16.row.col.f32.f16.f16.f32 "
        "{%0,%1,%2,%3}, {%4,%5,%6,%7}, {%8,%9}, {%0,%1,%2,%3};"
        : "+f"(c[0]), "+f"(c[1]), "+f"(c[2]), "+f"(c[3])
        : "r"(a0), "r"(a1), "r"(a2), "r"(a3), "r"(b0), "r"(b1));
}

// ---------------------------------------------------------------------------
__device__ __forceinline__ void stage_op(uint32_t dstb, const __half* __restrict__ S,
                                         int rowBase, int ld, int kt, int t) {
#pragma unroll
    for (int i = 0; i < 4; i++) {
        int task = t + i * NTHREADS;
        int row = task >> 3, k8 = task & 7;
        cpasync16(dstb + row * ROW_B + k8 * 16,
                  S + (size_t)(rowBase + row) * ld + kt + k8 * 8);
    }
}

// ---------------------------------------------------------------------------
// One 128x128x64 chunk (R9-proven form: within-step B ping-pong only).
// ---------------------------------------------------------------------------
__device__ __forceinline__ void compute_chunk(uint32_t As, uint32_t Bs,
                                              float acc[2][8][4], int warp, int lane) {
    const int wm = (warp & 3) * 32, wn = (warp >> 2) * 64;
    const uint32_t aBase = As + (uint32_t)(wm + (lane & 15)) * ROW_B
                              + (uint32_t)(lane >> 4) * 16;
    const uint32_t bBase = Bs + (uint32_t)(wn + (lane >> 4) * 8 + (lane & 7)) * ROW_B
                              + (uint32_t)((lane >> 3) & 1) * 16;
#pragma unroll
    for (int ks = 0; ks < 4; ks++) {
        const uint32_t ko = (uint32_t)ks * 32;
        uint32_t a0[4], a1[4], b[2][4];
        ldsm4(a0, aBase + ko);
        ldsm4(a1, aBase + 16 * ROW_B + ko);
        ldsm4(b[0], bBase + ko);
#pragma unroll
        for (int p = 0; p < 4; p++) {
            if (p < 3) ldsm4(b[(p + 1) & 1], bBase + (uint32_t)(p + 1) * (16 * ROW_B) + ko);
            const uint32_t* bp = b[p & 1];
            mma_f16(acc[0][2 * p],     a0[0], a0[1], a0[2], a0[3], bp[0], bp[1]);
            mma_f16(acc[0][2 * p + 1], a0[0], a0[1], a0[2], a0[3], bp[2], bp[3]);
            mma_f16(acc[1][2 * p],     a1[0], a1[1], a1[2], a1[3], bp[0], bp[1]);
            mma_f16(acc[1][2 * p + 1], a1[0], a1[1], a1[2], a1[3], bp[2], bp[3]);
        }
    }
}

// ---------------------------------------------------------------------------
// GEMM core. EPI: 0 fp32+colbias | 1 fp16+colbias | 2 fp16+rowbias |
//                 3 fp16=exp(alpha*acc) + fused column sums -> gS | 4 fp32.
// ---------------------------------------------------------------------------
template <int EPI>
__device__ __forceinline__ void tc_gemm(const __half* __restrict__ A,
                                        const __half* __restrict__ B,
                                        void* __restrict__ Cv,
                                        int Kdim, int lda, int ldb, int ldc,
                                        float alpha, const float* __restrict__ bias,
                                        int mBase, int nBase,
                                        float* __restrict__ gS = nullptr) {
    extern __shared__ char dsm[];
    const uint32_t sb = smem_u32(dsm);
    const int t = threadIdx.x, warp = t >> 5, lane = t & 31;

    float acc[2][8][4];
#pragma unroll
    for (int i = 0; i < 2; i++)
#pragma unroll
        for (int j = 0; j < 8; j++)
#pragma unroll
            for (int q = 0; q < 4; q++) acc[i][j][q] = 0.0f;

    const int NC = Kdim / BKH;

    stage_op(sb, A, mBase, lda, 0, t);
    stage_op(sb + TILE_B, B, nBase, ldb, 0, t);
    cpcommit();
    stage_op(sb + BUF_B, A, mBase, lda, BKH, t);
    stage_op(sb + BUF_B + TILE_B, B, nBase, ldb, BKH, t);
    cpcommit();

    uint32_t oCur = 0, oNext = BUF_B, oFree = 2u * BUF_B;

    for (int c = 0; c < NC; c++) {
        if (c + 1 < NC) cpwait<1>(); else cpwait<0>();
        __syncthreads();
        if (c + 2 < NC) {
            stage_op(sb + oFree, A, mBase, lda, (c + 2) * BKH, t);
            stage_op(sb + oFree + TILE_B, B, nBase, ldb, (c + 2) * BKH, t);
            cpcommit();
        }
        compute_chunk(sb + oCur, sb + oCur + TILE_B, acc, warp, lane);
        uint32_t tmp = oCur; oCur = oNext; oNext = oFree; oFree = tmp;
    }

    // epilogue
    const int g = lane >> 2, tg = lane & 3;
    const int wm = (warp & 3) * 32, wn = (warp >> 2) * 64;
    float cs[8][2];
    if (EPI == 3) {
#pragma unroll
        for (int j = 0; j < 8; j++) { cs[j][0] = 0.f; cs[j][1] = 0.f; }
    }
#pragma unroll
    for (int mi = 0; mi < 2; mi++) {
#pragma unroll
        for (int ni = 0; ni < 8; ni++) {
            const int row = mBase + wm + mi * 16 + g;
            const int col = nBase + wn + ni * 8 + tg * 2;
            float v0, v1, v2, v3;
            if (EPI == 0 || EPI == 1) {
                float2 bz = *(const float2*)(bias + col);
                v0 = fmaf(alpha, acc[mi][ni][0], bz.x);
                v1 = fmaf(alpha, acc[mi][ni][1], bz.y);
                v2 = fmaf(alpha, acc[mi][ni][2], bz.x);
                v3 = fmaf(alpha, acc[mi][ni][3], bz.y);
            } else if (EPI == 2) {
                float blo = bias[row], bhi = bias[row + 8];
                v0 = fmaf(alpha, acc[mi][ni][0], blo);
                v1 = fmaf(alpha, acc[mi][ni][1], blo);
                v2 = fmaf(alpha, acc[mi][ni][2], bhi);
                v3 = fmaf(alpha, acc[mi][ni][3], bhi);
            } else if (EPI == 3) {
                v0 = __expf(alpha * acc[mi][ni][0]);
                v1 = __expf(alpha * acc[mi][ni][1]);
                v2 = __expf(alpha * acc[mi][ni][2]);
                v3 = __expf(alpha * acc[mi][ni][3]);
                cs[ni][0] += v0 + v2;
                cs[ni][1] += v1 + v3;
            } else {
                v0 = alpha * acc[mi][ni][0];
                v1 = alpha * acc[mi][ni][1];
                v2 = alpha * acc[mi][ni][2];
                v3 = alpha * acc[mi][ni][3];
            }
            if (EPI == 0 || EPI == 4) {
                float* C = (float*)Cv;
                *(float2*)(C + (size_t)row * ldc + col)       = make_float2(v0, v1);
                *(float2*)(C + (size_t)(row + 8) * ldc + col) = make_float2(v2, v3);
            } else {
                __half* C = (__half*)Cv;
                *(__half2*)(C + (size_t)row * ldc + col)       = __floats2half2_rn(v0, v1);
                *(__half2*)(C + (size_t)(row + 8) * ldc + col) = __floats2half2_rn(v2, v3);
            }
        }
    }

    if (EPI == 3) {
        float* partial = reinterpret_cast<float*>(dsm);  // [4][128]
        __syncthreads();
#pragma unroll
        for (int ni = 0; ni < 8; ni++) {
#pragma unroll
            for (int j = 0; j < 2; j++) {
                float s = cs[ni][j];
                s += __shfl_down_sync(0xffffffffu, s, 16);
                s += __shfl_down_sync(0xffffffffu, s, 8);
                s += __shfl_down_sync(0xffffffffu, s, 4);
                if (lane < 4)
                    partial[(warp & 3) * 128 + wn + ni * 8 + lane * 2 + j] = s;
            }
        }
        __syncthreads();
        if (t < 128) {
            float S = partial[t] + partial[128 + t] + partial[256 + t] + partial[384 + t];
            atomicAdd(gS + nBase + t, S);
        }
    }
}

// ---------------------------------------------------------------------------
// Kernels
// ---------------------------------------------------------------------------

// Fused fp32 -> fp16 conversion (x, Wq|Wk|Wv); also zeroes g_S.
__global__ void __launch_bounds__(256) cvt_all_kernel(
    const float* __restrict__ x, const float* __restrict__ Wq,
    const float* __restrict__ Wk, const float* __restrict__ Wv) {
    const int XN4 = MTOK * DIM / 4, WN4 = DIM * DIM / 4;
    int i = blockIdx.x * blockDim.x + threadIdx.x;
    if (i < MTOK / 4)
        reinterpret_cast<float4*>(g_S)[i] = make_float4(0.f, 0.f, 0.f, 0.f);
    const float* src;
    __half* dst;
    int j;
    if (i < XN4)                { src = x;  dst = g_x;  j = i; }
    else if (i < XN4 + WN4)     { src = Wq; dst = g_wt; j = i - XN4; }
    else if (i < XN4 + 2 * WN4) { src = Wk; dst = g_wt + (size_t)DIM * DIM;     j = i - XN4 - WN4; }
    else if (i < XN4 + 3 * WN4) { src = Wv; dst = g_wt + (size_t)2 * DIM * DIM; j = i - XN4 - 2 * WN4; }
    else return;
    float4 v = reinterpret_cast<const float4*>(src)[j];
    reinterpret_cast<__half2*>(dst)[j * 2]     = __floats2half2_rn(v.x, v.y);
    reinterpret_cast<__half2*>(dst)[j * 2 + 1] = __floats2half2_rn(v.z, v.w);
}

// Q/K projections: z=0/1, fp16 out, per-column bias.
__global__ void __launch_bounds__(NTHREADS, 2) qk_kernel(
    const float* __restrict__ bq, const float* __restrict__ bk) {
    const float* bias = blockIdx.z == 0 ? bq : bk;
    __half* out       = blockIdx.z == 0 ? g_q : g_k;
    const __half* W   = g_wt + (size_t)blockIdx.z * DIM * DIM;
    tc_gemm<1>(g_x, W, out, DIM, DIM, DIM, DIM, 1.0f, bias,
               blockIdx.y * 128, blockIdx.x * 128);
}

// vT = Wv x^T + bv (row bias), fp16 out. Runs on the side stream.
__global__ void __launch_bounds__(NTHREADS, 2) vt_kernel(const float* __restrict__ bv) {
    tc_gemm<2>(g_wt + (size_t)2 * DIM * DIM, g_x, g_vt,
               DIM, DIM, DIM, MTOK, 1.0f, bv,
               blockIdx.y * 128, blockIdx.x * 128);
}

// e = exp(scores^T), fp16 out; fused column-sum atomics into g_S.
__global__ void __launch_bounds__(NTHREADS, 2) scoresT_kernel() {
    int b = blockIdx.z;
    tc_gemm<3>(g_k + (size_t)b * SEQ * DIM,
               g_q + (size_t)b * SEQ * DIM,
               g_wh + (size_t)b * SEQ * SEQ,
               DIM, DIM, DIM, SEQ, 0.03125f, nullptr,
               blockIdx.y * 128, blockIdx.x * 128,
               g_S + (size_t)b * SEQ);
}

// Scale vT columns by 1/S (uint4 loads, rcp inline).
__global__ void __launch_bounds__(256) vtscale_kernel() {
    size_t i = ((size_t)blockIdx.x * blockDim.x + threadIdx.x) * 8;
    int tok = (int)(i % MTOK);
    uint4* p = reinterpret_cast<uint4*>(g_vt + i);
    uint4 u = *p;
    float4 s0 = *reinterpret_cast<const float4*>(g_S + tok);
    float4 s1 = *reinterpret_cast<const float4*>(g_S + tok + 4);
    __half2* h = reinterpret_cast<__half2*>(&u);
    float2 v;
    v = __half22float2(h[0]); h[0] = __floats2half2_rn(v.x * __frcp_rn(s0.x), v.y * __frcp_rn(s0.y));
    v = __half22float2(h[1]); h[1] = __floats2half2_rn(v.x * __frcp_rn(s0.z), v.y * __frcp_rn(s0.w));
    v = __half22float2(h[2]); h[2] = __floats2half2_rn(v.x * __frcp_rn(s1.x), v.y * __frcp_rn(s1.y));
    v = __half22float2(h[3]); h[3] = __floats2half2_rn(v.x * __frcp_rn(s1.z), v.y * __frcp_rn(s1.w));
    *p = u;
}

// out = e . vT'^T, fp32 out.
__global__ void __launch_bounds__(NTHREADS, 2) out_kernel(float* __restrict__ out) {
    int b = blockIdx.z;
    tc_gemm<4>(g_wh + (size_t)b * SEQ * SEQ,
               g_vt + (size_t)b * SEQ,
               out + (size_t)b * SEQ * DIM,
               SEQ, SEQ, MTOK, DIM, 1.0f, nullptr,
               blockIdx.y * 128, blockIdx.x * 128);
}

// ---------------------------------------------------------------------------

extern "C" void kernel_launch(void* const* d_in, const int* in_sizes, int n_in,
                              void* d_out, int out_size) {
    (void)in_sizes; (void)n_in; (void)out_size;
    const float* x  = (const float*)d_in[0];
    const float* Wq = (const float*)d_in[1];
    const float* bq = (const float*)d_in[2];
    const float* Wk = (const float*)d_in[3];
    const float* bk = (const float*)d_in[4];
    const float* Wv = (const float*)d_in[5];
    const float* bv = (const float*)d_in[6];
    float* out = (float*)d_out;

    // Created once on the correctness call (outside graph capture); reused
    // every call. No device-memory allocation involved.
    static cudaStream_t s_vt = nullptr;
    static cudaEvent_t  ev_fork = nullptr, ev_join = nullptr;
    if (s_vt == nullptr) {
        cudaStreamCreateWithFlags(&s_vt, cudaStreamNonBlocking);
        cudaEventCreateWithFlags(&ev_fork, cudaEventDisableTiming);
        cudaEventCreateWithFlags(&ev_join, cudaEventDisableTiming);
        cudaFuncSetAttribute(qk_kernel,      cudaFuncAttributeMaxDynamicSharedMemorySize, SMEM_DYN);
        cudaFuncSetAttribute(vt_kernel,      cudaFuncAttributeMaxDynamicSharedMemorySize, SMEM_DYN);
        cudaFuncSetAttribute(scoresT_kernel, cudaFuncAttributeMaxDynamicSharedMemorySize, SMEM_DYN);
        cudaFuncSetAttribute(out_kernel,     cudaFuncAttributeMaxDynamicSharedMemorySize, SMEM_DYN);
    }

    {
        int total4 = (MTOK * DIM + 3 * DIM * DIM) / 4;
        cvt_all_kernel<<<(total4 + 255) / 256, 256>>>(x, Wq, Wk, Wv);
    }

    dim3 blk(NTHREADS);

    // Fork: vt on side stream, overlapping qk + scoresT tails.
    cudaEventRecord(ev_fork, 0);
    cudaStreamWaitEvent(s_vt, ev_fork, 0);
    vt_kernel<<<dim3(MTOK / 128, DIM / 128, 1), blk, SMEM_DYN, s_vt>>>(bv);
    cudaEventRecord(ev_join, s_vt);

    qk_kernel<<<dim3(DIM / 128, MTOK / 128, 2), blk, SMEM_DYN>>>(bq, bk);
    scoresT_kernel<<<dim3(SEQ / 128, SEQ / 128, BATCH), blk, SMEM_DYN>>>();

    // Join: vtscale needs both g_vt (side stream) and g_S (scoresT).
    cudaStreamWaitEvent(0, ev_join, 0);
    vtscale_kernel<<<dim3((int)((size_t)DIM * MTOK / 8 / 256)), dim3(256)>>>();
    out_kernel<<<dim3(DIM / 128, SEQ / 128, BATCH), blk, SMEM_DYN>>>(out);
}